// round 3
// baseline (speedup 1.0000x reference)
#include <cuda_runtime.h>

// LSTM_model_59244778881379 — autoregressive LSTM rollout, persistent per-CTA.
// B=8192, T=64, F=64, ORDER=16, K=256. fp32 throughout (fma.rn.f32x2 packed FMA).
//
// Each CTA owns MROWS=32 batch rows for the whole 64-step horizon.
//   SMEM inp_s[32][336] = [ x_t (64) | yp window (16) | h (256) ]  -> GEMM A operand
//   c state lives in registers (per-thread tile), h written back to inp_s each step.
// Thread tile: 8 rows x 4 hidden-units x 4 gates = 128 fp32 accumulators,
// packed as 64x u64 for fma.rn.f32x2 (2 FMA / instruction on sm_103a).
// Gate columns: z[:,g*256+u] for g in {i,f,g,o}; each thread owns matching
// quadruples so the c/h update is thread-local.

#define BATCH    8192
#define HOR      64
#define FDIM     64
#define ORD      16
#define KH       256
#define INPD     (FDIM + ORD + KH)   /* 336 */
#define GATE4    1024
#define MROWS    32
#define NTHREADS 256

__device__ __forceinline__ unsigned long long ffma2(unsigned long long a,
                                                    unsigned long long b,
                                                    unsigned long long c) {
    unsigned long long d;
    asm("fma.rn.f32x2 %0, %1, %2, %3;" : "=l"(d) : "l"(a), "l"(b), "l"(c));
    return d;
}
__device__ __forceinline__ unsigned long long pack2(float x) {
    unsigned long long d;
    asm("mov.b64 %0, {%1, %1};" : "=l"(d) : "f"(x));
    return d;
}
__device__ __forceinline__ unsigned long long pk2(float a, float b) {
    unsigned long long d;
    asm("mov.b64 %0, {%1, %2};" : "=l"(d) : "f"(a), "f"(b));
    return d;
}
__device__ __forceinline__ float2 upk(unsigned long long v) {
    float2 r;
    asm("mov.b64 {%0, %1}, %2;" : "=f"(r.x), "=f"(r.y) : "l"(v));
    return r;
}

union F4U { float4 v; unsigned long long u[2]; };

__device__ __forceinline__ float sigmoidf_(float x) {
    return 1.0f / (1.0f + __expf(-x));
}

// One 4-wide K chunk of the fused GEMM: acc[g][r][pair] += inp[r][k] * W[k][g*256+u].
__device__ __forceinline__ void gemm_chunk(
    unsigned long long (&acc)[4][8][2],
    const float (&inp)[MROWS][INPD],
    const float* __restrict__ wbase,   // weight matrix base, rows of 1024
    int kc, int coloff, int r0, int u0)
{
    float av[8][4];
#pragma unroll
    for (int r = 0; r < 8; r++) {
        float4 tv = *(const float4*)&inp[r0 + r][coloff + kc];
        av[r][0] = tv.x; av[r][1] = tv.y; av[r][2] = tv.z; av[r][3] = tv.w;
    }
#pragma unroll
    for (int kk = 0; kk < 4; kk++) {
        const float* wrow = wbase + (size_t)(kc + kk) * GATE4 + u0;
        F4U w[4];
#pragma unroll
        for (int g = 0; g < 4; g++)
            w[g].v = __ldg((const float4*)(wrow + g * KH));
#pragma unroll
        for (int r = 0; r < 8; r++) {
            unsigned long long a2 = pack2(av[r][kk]);
#pragma unroll
            for (int g = 0; g < 4; g++) {
                acc[g][r][0] = ffma2(a2, w[g].u[0], acc[g][r][0]);
                acc[g][r][1] = ffma2(a2, w[g].u[1], acc[g][r][1]);
            }
        }
    }
}

__global__ void __launch_bounds__(NTHREADS, 1)
lstm_rollout(const float* __restrict__ x, const float* __restrict__ y0,
             const float* __restrict__ Wk, const float* __restrict__ Wr,
             const float* __restrict__ bias, const float* __restrict__ dw,
             const float* __restrict__ db, float* __restrict__ out)
{
    __shared__ __align__(16) float inp_s[MROWS][INPD];
    __shared__ __align__(16) float ypb[MROWS][ORD];   // circular yp buffer

    const int tid  = threadIdx.x;
    const int rg   = tid >> 6;        // 0..3  (row group: 8 rows each)
    const int ug   = tid & 63;        // 0..63 (unit group: 4 units each)
    const int r0   = rg * 8;
    const int u0   = ug * 4;
    const int row0 = blockIdx.x * MROWS;

    // h region of inp_s starts at zero (h0 = 0)
    for (int i = tid; i < MROWS * KH; i += NTHREADS)
        inp_s[i >> 8][FDIM + ORD + (i & 255)] = 0.0f;
    // yp circular buffer <- y0 (head = 0: yp[j] = ypb[(head+j)&15])
    for (int i = tid; i < MROWS * ORD; i += NTHREADS) {
        int r = i >> 4, j = i & 15;
        ypb[r][j] = __ldg(y0 + (size_t)(row0 + r) * ORD + j);
    }

    // bias for this thread's 16 z-columns, held packed in registers
    unsigned long long bacc[4][2];
#pragma unroll
    for (int g = 0; g < 4; g++) {
        F4U b; b.v = __ldg((const float4*)(bias + g * KH + u0));
        bacc[g][0] = b.u[0]; bacc[g][1] = b.u[1];
    }
    const float db0 = __ldg(db);

    // c state (8 rows x 4 units) packed
    unsigned long long c2[8][2];
#pragma unroll
    for (int r = 0; r < 8; r++) { c2[r][0] = 0ull; c2[r][1] = 0ull; }

    int head = 0;
    __syncthreads();

    for (int t = 0; t < HOR; t++) {
        // ---- stage x_t and ordered yp window into inp_s ----
        for (int i = tid; i < MROWS * (FDIM / 4); i += NTHREADS) {
            int r = i >> 4, f4 = i & 15;
            float4 xv = __ldg((const float4*)(x + ((size_t)(row0 + r) * HOR + t) * FDIM + f4 * 4));
            *(float4*)&inp_s[r][f4 * 4] = xv;
        }
        for (int i = tid; i < MROWS * ORD; i += NTHREADS) {
            int r = i >> 4, j = i & 15;
            inp_s[r][FDIM + j] = ypb[r][(head + j) & 15];
        }
        __syncthreads();

        // ---- fused GEMM: z = [x|yp] @ Wk + h @ Wr + bias ----
        unsigned long long acc[4][8][2];
#pragma unroll
        for (int g = 0; g < 4; g++)
#pragma unroll
            for (int r = 0; r < 8; r++) {
                acc[g][r][0] = bacc[g][0];
                acc[g][r][1] = bacc[g][1];
            }

#pragma unroll 1
        for (int kc = 0; kc < FDIM + ORD; kc += 4)
            gemm_chunk(acc, inp_s, Wk, kc, 0, r0, u0);
#pragma unroll 1
        for (int kc = 0; kc < KH; kc += 4)
            gemm_chunk(acc, inp_s, Wr, kc, FDIM + ORD, r0, u0);

        // ---- gates + state update (thread-local) ----
        float hv[8][4];
#pragma unroll
        for (int r = 0; r < 8; r++) {
#pragma unroll
            for (int p = 0; p < 2; p++) {
                float2 iv = upk(acc[0][r][p]);
                float2 fv = upk(acc[1][r][p]);
                float2 gv = upk(acc[2][r][p]);
                float2 ov = upk(acc[3][r][p]);
                float2 cc = upk(c2[r][p]);
                float i0 = sigmoidf_(iv.x), i1 = sigmoidf_(iv.y);
                float f0 = sigmoidf_(fv.x), f1 = sigmoidf_(fv.y);
                float g0 = tanhf(gv.x),     g1 = tanhf(gv.y);
                float o0 = sigmoidf_(ov.x), o1 = sigmoidf_(ov.y);
                float cn0 = f0 * cc.x + i0 * g0;
                float cn1 = f1 * cc.y + i1 * g1;
                c2[r][p] = pk2(cn0, cn1);
                hv[r][2 * p + 0] = o0 * tanhf(cn0);
                hv[r][2 * p + 1] = o1 * tanhf(cn1);
            }
        }

        __syncthreads();   // all GEMM reads of inp_s done before h overwrite
#pragma unroll
        for (int r = 0; r < 8; r++)
            *(float4*)&inp_s[r0 + r][FDIM + ORD + u0] =
                make_float4(hv[r][0], hv[r][1], hv[r][2], hv[r][3]);
        __syncthreads();   // h_t fully visible

        // ---- pred = h @ dense_w + b ; shift into yp window ----
        {
            int r = tid >> 3, j = tid & 7;   // 32 rows x 8 lanes
            float s = 0.f;
#pragma unroll
            for (int u = j; u < KH; u += 8)
                s += inp_s[r][FDIM + ORD + u] * __ldg(dw + u);
            s += __shfl_down_sync(0xffffffffu, s, 4, 8);
            s += __shfl_down_sync(0xffffffffu, s, 2, 8);
            s += __shfl_down_sync(0xffffffffu, s, 1, 8);
            if (j == 0) {
                float p = s + db0;
                out[(size_t)(row0 + r) * HOR + t] = p;
                ypb[r][(head + 15) & 15] = p;   // new head slot
            }
        }
        head = (head + 15) & 15;   // head -= 1 (mod 16), uniform
        __syncthreads();           // ypb write visible before next staging
    }
}

extern "C" void kernel_launch(void* const* d_in, const int* in_sizes, int n_in,
                              void* d_out, int out_size) {
    const float* x    = (const float*)d_in[0];
    const float* y0   = (const float*)d_in[1];
    const float* Wk   = (const float*)d_in[2];   // [80, 1024]
    const float* Wr   = (const float*)d_in[3];   // [256, 1024]
    const float* bias = (const float*)d_in[4];   // [1024]
    const float* dw   = (const float*)d_in[5];   // [256, 1]
    const float* db   = (const float*)d_in[6];   // [1]
    float* out = (float*)d_out;                  // [8192, 64, 1]
    lstm_rollout<<<BATCH / MROWS, NTHREADS>>>(x, y0, Wk, Wr, bias, dw, db, out);
}